// round 11
// baseline (speedup 1.0000x reference)
#include <cuda_runtime.h>
#include <cuda_bf16.h>
#include <cuda_fp16.h>
#include <cstdint>

#define N_NODES 50000
#define N_EDGES 800000
#define HID 128
#define COUT 40
#define SETUP_BLOCKS 148   // one block per SM: co-residency unconditional
#define NB_SCAN 196        // ceil(50000/256)

typedef unsigned long long ull;

// ---------------- device scratch (static, allocation-free) ----------------
__device__ float g_dis[N_NODES];
__device__ float g_cwa[N_NODES];         // sum over out-edges of dis[col]
__device__ int   g_cnt[N_NODES];
__device__ int   g_off[N_NODES + 1];
__device__ int   g_cur[N_NODES];
__device__ int   g_bsum[NB_SCAN];
__device__ __align__(16) unsigned g_emeta[N_EDGES]; // {fp16 norm | 16-bit src}
__device__ float g_v[HID];               // weighted h2 reduction
__device__ int   g_flag;                 // 1 = edge_index is int64, 0 = int32
__device__ unsigned g_barcnt;            // grid barrier arrive counter (self-reset)
__device__ volatile unsigned g_sense;    // grid barrier phase (monotonic across replays)
__device__ unsigned g_done;              // wred completion counter (self-reset)
__device__ float g_bufA[N_NODES * HID];  // xw bf16 / int2 staging
__device__ float g_bufB[N_NODES * HID];  // h bf16 scratch
// W in mma B-fragment layout: [layer][lvl(hi/lo)][kstep 8][lane 32][nb 16] uint2
__device__ __align__(16) uint2 g_wfrag[2 * 2 * 8 * 32 * 16];

__device__ __forceinline__ void decode_edge(const void* ei, int e, int& r, int& c) {
    if (g_flag) {
        const long long* p = (const long long*)ei;
        r = (int)p[e];
        c = (int)p[N_EDGES + e];
    } else {
        const int* p = (const int*)ei;
        r = p[e];
        c = p[N_EDGES + e];
    }
}

__device__ __forceinline__ uint32_t smem_u32(const void* p) {
    uint32_t a;
    asm("{ .reg .u64 t; cvta.to.shared.u64 t, %1; cvt.u32.u64 %0, t; }" : "=r"(a) : "l"(p));
    return a;
}
__device__ __forceinline__ unsigned pack_bf16(float a, float b) {
    __nv_bfloat162 t = __float22bfloat162_rn(make_float2(a, b));
    return *(unsigned*)&t;
}

// Software grid barrier; 148 blocks = 1/SM, co-resident by construction.
__device__ __forceinline__ void grid_bar(unsigned target) {
    __threadfence();
    __syncthreads();
    if (threadIdx.x == 0) {
        unsigned my = atomicAdd(&g_barcnt, 1u);
        if (my == SETUP_BLOCKS - 1) {
            g_barcnt = 0;
            __threadfence();
            g_sense = target;
        } else {
            while (g_sense != target) { __nanosleep(64); }
        }
        __threadfence();
    }
    __syncthreads();
}

// ---------------- fused CSR-build + W-fragment prep (one launch) -----------
__global__ __launch_bounds__(256) void k_setup(const void* __restrict__ ei,
                                               int2* __restrict__ stage,
                                               const float* __restrict__ W0,
                                               const float* __restrict__ W1)
{
    __shared__ int s[256];
    int tid = threadIdx.x;
    int b = blockIdx.x;
    unsigned base = g_sense;

    // --- phase 0: zero counters, detect index width, build W fragments ---
    for (int i = b * 256 + tid; i < N_NODES; i += SETUP_BLOCKS * 256) {
        g_cnt[i] = 0;
        g_cwa[i] = 0.f;
    }
    if (b == 0 && tid < HID) g_v[tid] = 0.f;
    if (b == 0 && tid < 32) {
        const unsigned* u = (const unsigned*)ei;
        unsigned nz = (u[2 * tid + 1] != 0u) | (u[2 * (tid + 32) + 1] != 0u);
        unsigned any = __ballot_sync(0xffffffffu, nz);
        if (tid == 0) g_flag = (any == 0u) ? 1 : 0;
    }
    // W fragments: 8192 slots = (layer,nb,ks,lane); each writes hi+lo uint2
    for (int lin = b * 256 + tid; lin < 8192; lin += SETUP_BLOCKS * 256) {
        int lane = lin & 31;
        int ks = (lin >> 5) & 7;
        int nb = (lin >> 8) & 15;
        int layer = (lin >> 12) & 1;
        const float* W = layer ? W1 : W0;
        int g = lane >> 2, tg = lane & 3;
        int n = nb * 8 + g;
        int k0 = ks * 16 + tg * 2;
        float w00 = W[k0 * 128 + n],       w01 = W[(k0 + 1) * 128 + n];
        float w10 = W[(k0 + 8) * 128 + n], w11 = W[(k0 + 9) * 128 + n];
        __nv_bfloat16 h00 = __float2bfloat16(w00), h01 = __float2bfloat16(w01);
        __nv_bfloat16 h10 = __float2bfloat16(w10), h11 = __float2bfloat16(w11);
        unsigned b0h = (unsigned)*(unsigned short*)&h00 | ((unsigned)*(unsigned short*)&h01 << 16);
        unsigned b1h = (unsigned)*(unsigned short*)&h10 | ((unsigned)*(unsigned short*)&h11 << 16);
        unsigned b0l = pack_bf16(w00 - __bfloat162float(h00), w01 - __bfloat162float(h01));
        unsigned b1l = pack_bf16(w10 - __bfloat162float(h10), w11 - __bfloat162float(h11));
        int ih = (((layer * 2 + 0) * 8 + ks) * 32 + lane) * 16 + nb;
        int il = (((layer * 2 + 1) * 8 + ks) * 32 + lane) * 16 + nb;
        g_wfrag[ih] = make_uint2(b0h, b1h);
        g_wfrag[il] = make_uint2(b0l, b1l);
    }
    grid_bar(base + 1);

    // --- phase 1: decode + histogram ---
    for (int e = b * 256 + tid; e < N_EDGES; e += SETUP_BLOCKS * 256) {
        int r, c;
        decode_edge(ei, e, r, c);
        stage[e] = make_int2(r, c);
        atomicAdd(&g_cnt[c], 1);
    }
    grid_bar(base + 2);

    // --- phase 2: local scans (grid-stride over 196 chunks) ---
    for (int ch = b; ch < NB_SCAN; ch += SETUP_BLOCKS) {
        int i = ch * 256 + tid;
        int v = (i < N_NODES) ? g_cnt[i] : 0;
        s[tid] = v;
        __syncthreads();
        for (int d = 1; d < 256; d <<= 1) {
            int t = (tid >= d) ? s[tid - d] : 0;
            __syncthreads();
            s[tid] += t;
            __syncthreads();
        }
        if (i < N_NODES) g_off[i] = s[tid] - v;
        if (tid == 255) g_bsum[ch] = s[255];
        __syncthreads();
    }
    grid_bar(base + 3);

    // --- phase 3: redundant chunk-sum scan, apply prefixes, derive dis/cur ---
    {
        int v = (tid < NB_SCAN) ? g_bsum[tid] : 0;
        s[tid] = v;
        __syncthreads();
        for (int d = 1; d < 256; d <<= 1) {
            int t = (tid >= d) ? s[tid - d] : 0;
            __syncthreads();
            s[tid] += t;
            __syncthreads();
        }
        for (int ch = b; ch < NB_SCAN; ch += SETUP_BLOCKS) {
            int pre = (ch == 0) ? 0 : s[ch - 1];
            int i = ch * 256 + tid;
            if (i < N_NODES) {
                int o = g_off[i] + pre;
                g_off[i] = o;
                g_cur[i] = o;
                g_dis[i] = rsqrtf((float)g_cnt[i] + 1.0f);
            }
            if (i == 0) g_off[N_NODES] = N_EDGES;
        }
    }
    grid_bar(base + 4);

    // --- phase 4: fill CSR + layer-3 collapse weights ---
    for (int e = b * 256 + tid; e < N_EDGES; e += SETUP_BLOCKS * 256) {
        int2 rc = stage[e];
        float dr = g_dis[rc.x], dc = g_dis[rc.y];
        int pos = atomicAdd(&g_cur[rc.y], 1);
        unsigned short hn = __half_as_ushort(__float2half_rn(dr * dc));
        g_emeta[pos] = (unsigned)rc.x | ((unsigned)hn << 16);
        atomicAdd(&g_cwa[rc.x], dc);
    }
}

// ---------------- mma.sync GEMM: [N,128] @ [128,128] -> xw bf16 ------------
// 128x128 tile, 8 warps (warp = 16 rows x 128 cols), A staged bf16 in
// swizzled smem + ldmatrix, W from precomputed B-fragments, W hi+lo passes.
__global__ __launch_bounds__(256) void k_gemm_mma(
    const void* __restrict__ Ain, int a_bf16,
    const uint2* __restrict__ wfrag,    // this layer's [lvl][ks][lane][nb]
    __nv_bfloat16* __restrict__ xwh)
{
    __shared__ __align__(16) __nv_bfloat16 sA[128 * 128];  // 32KB, 16B-chunk XOR swizzle
    int tid = threadIdx.x;
    int lane = tid & 31;
    int w = tid >> 5;
    int rb = blockIdx.x * 128;

    // --- stage A tile as bf16 (thread = half a row) ---
    {
        int row = tid >> 1;
        int hf = tid & 1;
        int gr = rb + row;
        if (a_bf16) {
            const uint4* src = (const uint4*)Ain + (size_t)gr * 16 + hf * 8;
#pragma unroll
            for (int c = 0; c < 8; c++) {
                uint4 v = make_uint4(0u, 0u, 0u, 0u);
                if (gr < N_NODES) v = src[c];
                int ch = hf * 8 + c;
                *(uint4*)&sA[row * 128 + (ch ^ (row & 7)) * 8] = v;
            }
        } else {
            const float4* src = (const float4*)Ain + (size_t)gr * 32 + hf * 16;
#pragma unroll
            for (int c = 0; c < 8; c++) {
                uint4 v = make_uint4(0u, 0u, 0u, 0u);
                if (gr < N_NODES) {
                    float4 f0 = src[2 * c];
                    float4 f1 = src[2 * c + 1];
                    v.x = pack_bf16(f0.x, f0.y);
                    v.y = pack_bf16(f0.z, f0.w);
                    v.z = pack_bf16(f1.x, f1.y);
                    v.w = pack_bf16(f1.z, f1.w);
                }
                int ch = hf * 8 + c;
                *(uint4*)&sA[row * 128 + (ch ^ (row & 7)) * 8] = v;
            }
        }
    }
    __syncthreads();

    float acc[16][4];
#pragma unroll
    for (int i = 0; i < 16; i++)
#pragma unroll
        for (int j = 0; j < 4; j++) acc[i][j] = 0.f;

    // ldmatrix address (fixed per thread per kstep): matrix m = lane>>3
    int m = lane >> 3, r_in = lane & 7;
    int row_m = w * 16 + (m & 1) * 8 + r_in;

#pragma unroll
    for (int ks = 0; ks < 8; ks++) {
        unsigned a0, a1, a2, a3;
        int chunk = ks * 2 + (m >> 1);
        uint32_t addr = smem_u32(&sA[row_m * 128 + (chunk ^ r_in) * 8]);
        asm volatile("ldmatrix.sync.aligned.m8n8.x4.shared.b16 {%0,%1,%2,%3}, [%4];"
                     : "=r"(a0), "=r"(a1), "=r"(a2), "=r"(a3) : "r"(addr));
#pragma unroll
        for (int lvl = 0; lvl < 2; lvl++) {
            const uint4* wp = (const uint4*)(wfrag + ((lvl * 8 + ks) * 32 + lane) * 16);
#pragma unroll
            for (int np = 0; np < 8; np++) {
                uint4 bb = wp[np];
                asm volatile(
                    "mma.sync.aligned.m16n8k16.row.col.f32.bf16.bf16.f32 "
                    "{%0,%1,%2,%3}, {%4,%5,%6,%7}, {%8,%9}, {%0,%1,%2,%3};"
                    : "+f"(acc[2 * np][0]), "+f"(acc[2 * np][1]),
                      "+f"(acc[2 * np][2]), "+f"(acc[2 * np][3])
                    : "r"(a0), "r"(a1), "r"(a2), "r"(a3), "r"(bb.x), "r"(bb.y));
                asm volatile(
                    "mma.sync.aligned.m16n8k16.row.col.f32.bf16.bf16.f32 "
                    "{%0,%1,%2,%3}, {%4,%5,%6,%7}, {%8,%9}, {%0,%1,%2,%3};"
                    : "+f"(acc[2 * np + 1][0]), "+f"(acc[2 * np + 1][1]),
                      "+f"(acc[2 * np + 1][2]), "+f"(acc[2 * np + 1][3])
                    : "r"(a0), "r"(a1), "r"(a2), "r"(a3), "r"(bb.z), "r"(bb.w));
            }
        }
    }
    __syncthreads();   // done reading sA; reuse as D staging

    // --- stage D (bf16) into swizzled smem ---
    {
        int g = lane >> 2, tg = lane & 3;
        int r0 = w * 16 + g;
        int r1 = r0 + 8;
#pragma unroll
        for (int nb = 0; nb < 16; nb++) {
            *(unsigned*)&sA[r0 * 128 + (nb ^ (r0 & 7)) * 8 + tg * 2] =
                pack_bf16(acc[nb][0], acc[nb][1]);
            *(unsigned*)&sA[r1 * 128 + (nb ^ (r1 & 7)) * 8 + tg * 2] =
                pack_bf16(acc[nb][2], acc[nb][3]);
        }
    }
    __syncthreads();

    // --- coalesced copy out ---
    {
        int row = tid >> 1;
        int hf = tid & 1;
        int gr = rb + row;
        if (gr < N_NODES) {
            uint4* dst = (uint4*)xwh + (size_t)gr * 16 + hf * 8;
#pragma unroll
            for (int c = 0; c < 8; c++) {
                int ch = hf * 8 + c;
                dst[c] = *(uint4*)&sA[row * 128 + (ch ^ (row & 7)) * 8];
            }
        }
    }
}

// ---------------- CSR aggregate (warp per node, bf16 in/out) ---------------
__device__ __forceinline__ void acc_bf16(float4& acc, uint2 v, float nw) {
    float f0 = __uint_as_float(v.x << 16);
    float f1 = __uint_as_float(v.x & 0xFFFF0000u);
    float f2 = __uint_as_float(v.y << 16);
    float f3 = __uint_as_float(v.y & 0xFFFF0000u);
    acc.x += f0 * nw; acc.y += f1 * nw; acc.z += f2 * nw; acc.w += f3 * nw;
}
__device__ __forceinline__ float meta_norm(unsigned m) {
    return __half2float(__ushort_as_half((unsigned short)(m >> 16)));
}

__global__ __launch_bounds__(256) void k_agg128(
    const __nv_bfloat16* __restrict__ xwh, const float* __restrict__ bias,
    __nv_bfloat16* __restrict__ h)
{
    int w = blockIdx.x * 8 + (threadIdx.x >> 5);
    int lane = threadIdx.x & 31;
    if (w >= N_NODES) return;
    const uint2* xw2 = (const uint2*)xwh;
    float d = g_dis[w];
    float4 acc = make_float4(0.f, 0.f, 0.f, 0.f);
    acc_bf16(acc, xw2[w * 32 + lane], d * d);
    int beg = g_off[w], end = g_off[w + 1];
    int e = beg;
    while ((e & 3) && e < end) {
        unsigned m = g_emeta[e];
        acc_bf16(acc, xw2[(int)(m & 0xFFFFu) * 32 + lane], meta_norm(m));
        e++;
    }
    for (; e + 4 <= end; e += 4) {
        uint4 mm = *(const uint4*)&g_emeta[e];
        uint2 v0 = xw2[(int)(mm.x & 0xFFFFu) * 32 + lane];
        uint2 v1 = xw2[(int)(mm.y & 0xFFFFu) * 32 + lane];
        uint2 v2 = xw2[(int)(mm.z & 0xFFFFu) * 32 + lane];
        uint2 v3 = xw2[(int)(mm.w & 0xFFFFu) * 32 + lane];
        acc_bf16(acc, v0, meta_norm(mm.x));
        acc_bf16(acc, v1, meta_norm(mm.y));
        acc_bf16(acc, v2, meta_norm(mm.z));
        acc_bf16(acc, v3, meta_norm(mm.w));
    }
    for (; e < end; e++) {
        unsigned m = g_emeta[e];
        acc_bf16(acc, xw2[(int)(m & 0xFFFFu) * 32 + lane], meta_norm(m));
    }
    float4 bb = ((const float4*)bias)[lane];
    acc.x = fmaxf(acc.x + bb.x, 0.f);
    acc.y = fmaxf(acc.y + bb.y, 0.f);
    acc.z = fmaxf(acc.z + bb.z, 0.f);
    acc.w = fmaxf(acc.w + bb.w, 0.f);
    uint2 st;
    st.x = pack_bf16(acc.x, acc.y);
    st.y = pack_bf16(acc.z, acc.w);
    ((uint2*)h)[w * 32 + lane] = st;
}

// --------- layer-3 collapse + fused finish (last block computes out) -------
#define WRED_BLOCKS ((N_NODES + 127) / 128)   // 391
__global__ __launch_bounds__(256) void k_wred(
    const __nv_bfloat16* __restrict__ h2, const float* __restrict__ W2,
    const float* __restrict__ b2, float* __restrict__ out)
{
    __shared__ float sv[256];
    __shared__ unsigned s_rank;
    int tid = threadIdx.x;
    int k = tid & 127;
    int hf = tid >> 7;
    float acc = 0.f;
    int m0 = blockIdx.x * 128;
    int mend = min(m0 + 128, N_NODES);
    for (int m = m0 + hf; m < mend; m += 2) {
        float d = g_dis[m];
        float wn = d * (g_cwa[m] + d);
        acc += wn * __bfloat162float(h2[m * HID + k]);
    }
    sv[tid] = acc;
    __syncthreads();
    if (hf == 0) atomicAdd(&g_v[k], acc + sv[128 + k]);
    __threadfence();
    __syncthreads();
    if (tid == 0) s_rank = atomicAdd(&g_done, 1u);
    __syncthreads();
    if (s_rank == WRED_BLOCKS - 1) {
        if (tid == 0) g_done = 0;
        __threadfence();
        if (tid < COUT) {
            float a = 0.f;
#pragma unroll 4
            for (int j = 0; j < HID; j++) a += __ldcg(&g_v[j]) * W2[j * COUT + tid];
            out[tid] = b2[tid] + a * (1.0f / (float)N_NODES);
        }
    }
}

// ---------------- launch ----------------------------------------------------
extern "C" void kernel_launch(void* const* d_in, const int* in_sizes, int n_in,
                              void* d_out, int out_size)
{
    const float* x  = (const float*)d_in[0];
    const void*  ei = d_in[1];
    const float* W0 = (const float*)d_in[2];
    const float* b0 = (const float*)d_in[3];
    const float* W1 = (const float*)d_in[4];
    const float* b1 = (const float*)d_in[5];
    const float* W2 = (const float*)d_in[6];
    const float* b2 = (const float*)d_in[7];
    float* out = (float*)d_out;

    float* bufA; cudaGetSymbolAddress((void**)&bufA, g_bufA);
    float* bufB; cudaGetSymbolAddress((void**)&bufB, g_bufB);
    uint2* wfrag; cudaGetSymbolAddress((void**)&wfrag, g_wfrag);

    const int gemmBlocks = (N_NODES + 127) / 128;   // 391
    const int aggBlocks  = (N_NODES + 7) / 8;       // 6250
    const int WFRAG_PER_LAYER = 2 * 8 * 32 * 16;    // 8192 uint2

    // --- fused CSR build + W fragment prep (1 launch) ---
    k_setup<<<SETUP_BLOCKS, 256>>>(ei, (int2*)bufA, W0, W1);

    __nv_bfloat16* xwh = (__nv_bfloat16*)bufA;
    __nv_bfloat16* hb  = (__nv_bfloat16*)bufB;

    // --- layer 1: x (fp32) -> hb (h1, bf16) ---
    k_gemm_mma<<<gemmBlocks, 256>>>(x, 0, wfrag, xwh);
    k_agg128<<<aggBlocks, 256>>>(xwh, b0, hb);

    // --- layer 2: hb (bf16) -> hb (h2, bf16) ---
    k_gemm_mma<<<gemmBlocks, 256>>>(hb, 1, wfrag + WFRAG_PER_LAYER, xwh);
    k_agg128<<<aggBlocks, 256>>>(xwh, b1, hb);

    // --- layer 3 (collapsed) + finish fused ---
    k_wred<<<WRED_BLOCKS, 256>>>(hb, W2, b2, out);
}

// round 12
// speedup vs baseline: 1.5713x; 1.5713x over previous
#include <cuda_runtime.h>
#include <cuda_bf16.h>
#include <cuda_fp16.h>
#include <cstdint>

#define N_NODES 50000
#define N_EDGES 800000
#define HID 128
#define COUT 40
#define SETUP_BLOCKS 148   // one block per SM: co-residency unconditional
#define NB_SCAN 196        // ceil(50000/256)
#define GEMM_SMEM (64 * 1024 + 32 * 1024)   // sW (64KB) + sA (32KB)

typedef unsigned long long ull;

// ---------------- device scratch (static, allocation-free) ----------------
__device__ float g_dis[N_NODES];
__device__ float g_cwa[N_NODES];         // sum over out-edges of dis[col]
__device__ int   g_cnt[N_NODES];
__device__ int   g_off[N_NODES + 1];
__device__ int   g_cur[N_NODES];
__device__ int   g_bsum[NB_SCAN];
__device__ __align__(16) unsigned g_emeta[N_EDGES]; // {fp16 norm | 16-bit src}
__device__ float g_v[HID];               // weighted h2 reduction
__device__ int   g_flag;                 // 1 = edge_index is int64, 0 = int32
__device__ unsigned g_barcnt;            // grid barrier arrive counter (self-reset)
__device__ volatile unsigned g_sense;    // grid barrier phase (monotonic across replays)
__device__ unsigned g_done;              // wred completion counter (self-reset)
__device__ float g_bufA[N_NODES * HID];  // xw bf16 / int2 staging
__device__ float g_bufB[N_NODES * HID];  // h bf16 scratch
// W fragments, smem-image layout per layer: uint2[ ((lvl*8+ks)*8+np)*32+lane ][2]
__device__ __align__(16) uint2 g_wfrag[2 * 8192];

__device__ __forceinline__ void decode_edge(const void* ei, int e, int& r, int& c) {
    if (g_flag) {
        const long long* p = (const long long*)ei;
        r = (int)p[e];
        c = (int)p[N_EDGES + e];
    } else {
        const int* p = (const int*)ei;
        r = p[e];
        c = p[N_EDGES + e];
    }
}

__device__ __forceinline__ uint32_t smem_u32(const void* p) {
    uint32_t a;
    asm("{ .reg .u64 t; cvta.to.shared.u64 t, %1; cvt.u32.u64 %0, t; }" : "=r"(a) : "l"(p));
    return a;
}
__device__ __forceinline__ unsigned pack_bf16(float a, float b) {
    __nv_bfloat162 t = __float22bfloat162_rn(make_float2(a, b));
    return *(unsigned*)&t;
}

// Software grid barrier; 148 blocks = 1/SM, co-resident by construction.
__device__ __forceinline__ void grid_bar(unsigned target) {
    __threadfence();
    __syncthreads();
    if (threadIdx.x == 0) {
        unsigned my = atomicAdd(&g_barcnt, 1u);
        if (my == SETUP_BLOCKS - 1) {
            g_barcnt = 0;
            __threadfence();
            g_sense = target;
        } else {
            while (g_sense != target) { __nanosleep(64); }
        }
        __threadfence();
    }
    __syncthreads();
}

// ---------------- fused CSR-build + W-fragment prep (one launch) -----------
__global__ __launch_bounds__(256) void k_setup(const void* __restrict__ ei,
                                               int2* __restrict__ stage,
                                               const float* __restrict__ W0,
                                               const float* __restrict__ W1)
{
    __shared__ int s[256];
    int tid = threadIdx.x;
    int b = blockIdx.x;
    unsigned base = g_sense;

    // --- phase 0: zero counters, detect index width, build W fragments ---
    for (int i = b * 256 + tid; i < N_NODES; i += SETUP_BLOCKS * 256) {
        g_cnt[i] = 0;
        g_cwa[i] = 0.f;
    }
    if (b == 0 && tid < HID) g_v[tid] = 0.f;
    if (b == 0 && tid < 32) {
        const unsigned* u = (const unsigned*)ei;
        unsigned nz = (u[2 * tid + 1] != 0u) | (u[2 * (tid + 32) + 1] != 0u);
        unsigned any = __ballot_sync(0xffffffffu, nz);
        if (tid == 0) g_flag = (any == 0u) ? 1 : 0;
    }
    // W fragments: 8192 slots = (layer,nb,ks,lane); each writes hi+lo uint2.
    // Layout matches the per-CTA smem image (lane-fastest for conflict-free LDS.128):
    //   uint2 idx = layer*8192 + (((lvl*8+ks)*8 + (nb>>1))*32 + lane)*2 + (nb&1)
    for (int lin = b * 256 + tid; lin < 8192; lin += SETUP_BLOCKS * 256) {
        int lane = lin & 31;
        int ks = (lin >> 5) & 7;
        int nb = (lin >> 8) & 15;
        int layer = (lin >> 12) & 1;
        const float* W = layer ? W1 : W0;
        int g = lane >> 2, tg = lane & 3;
        int n = nb * 8 + g;
        int k0 = ks * 16 + tg * 2;
        float w00 = W[k0 * 128 + n],       w01 = W[(k0 + 1) * 128 + n];
        float w10 = W[(k0 + 8) * 128 + n], w11 = W[(k0 + 9) * 128 + n];
        __nv_bfloat16 h00 = __float2bfloat16(w00), h01 = __float2bfloat16(w01);
        __nv_bfloat16 h10 = __float2bfloat16(w10), h11 = __float2bfloat16(w11);
        unsigned b0h = (unsigned)*(unsigned short*)&h00 | ((unsigned)*(unsigned short*)&h01 << 16);
        unsigned b1h = (unsigned)*(unsigned short*)&h10 | ((unsigned)*(unsigned short*)&h11 << 16);
        unsigned b0l = pack_bf16(w00 - __bfloat162float(h00), w01 - __bfloat162float(h01));
        unsigned b1l = pack_bf16(w10 - __bfloat162float(h10), w11 - __bfloat162float(h11));
        int np = nb >> 1, half = nb & 1;
        int ih = layer * 8192 + (((0 * 8 + ks) * 8 + np) * 32 + lane) * 2 + half;
        int il = layer * 8192 + (((1 * 8 + ks) * 8 + np) * 32 + lane) * 2 + half;
        g_wfrag[ih] = make_uint2(b0h, b1h);
        g_wfrag[il] = make_uint2(b0l, b1l);
    }
    grid_bar(base + 1);

    // --- phase 1: decode + histogram ---
    for (int e = b * 256 + tid; e < N_EDGES; e += SETUP_BLOCKS * 256) {
        int r, c;
        decode_edge(ei, e, r, c);
        stage[e] = make_int2(r, c);
        atomicAdd(&g_cnt[c], 1);
    }
    grid_bar(base + 2);

    // --- phase 2: local scans (grid-stride over 196 chunks) ---
    for (int ch = b; ch < NB_SCAN; ch += SETUP_BLOCKS) {
        int i = ch * 256 + tid;
        int v = (i < N_NODES) ? g_cnt[i] : 0;
        s[tid] = v;
        __syncthreads();
        for (int d = 1; d < 256; d <<= 1) {
            int t = (tid >= d) ? s[tid - d] : 0;
            __syncthreads();
            s[tid] += t;
            __syncthreads();
        }
        if (i < N_NODES) g_off[i] = s[tid] - v;
        if (tid == 255) g_bsum[ch] = s[255];
        __syncthreads();
    }
    grid_bar(base + 3);

    // --- phase 3: redundant chunk-sum scan, apply prefixes, derive dis/cur ---
    {
        int v = (tid < NB_SCAN) ? g_bsum[tid] : 0;
        s[tid] = v;
        __syncthreads();
        for (int d = 1; d < 256; d <<= 1) {
            int t = (tid >= d) ? s[tid - d] : 0;
            __syncthreads();
            s[tid] += t;
            __syncthreads();
        }
        for (int ch = b; ch < NB_SCAN; ch += SETUP_BLOCKS) {
            int pre = (ch == 0) ? 0 : s[ch - 1];
            int i = ch * 256 + tid;
            if (i < N_NODES) {
                int o = g_off[i] + pre;
                g_off[i] = o;
                g_cur[i] = o;
                g_dis[i] = rsqrtf((float)g_cnt[i] + 1.0f);
            }
            if (i == 0) g_off[N_NODES] = N_EDGES;
        }
    }
    grid_bar(base + 4);

    // --- phase 4: fill CSR + layer-3 collapse weights ---
    for (int e = b * 256 + tid; e < N_EDGES; e += SETUP_BLOCKS * 256) {
        int2 rc = stage[e];
        float dr = g_dis[rc.x], dc = g_dis[rc.y];
        int pos = atomicAdd(&g_cur[rc.y], 1);
        unsigned short hn = __half_as_ushort(__float2half_rn(dr * dc));
        g_emeta[pos] = (unsigned)rc.x | ((unsigned)hn << 16);
        atomicAdd(&g_cwa[rc.x], dc);
    }
}

// ---------------- mma.sync GEMM: [N,128] @ [128,128] -> xw bf16 ------------
// 128x128 tile, 8 warps; A staged bf16 in swizzled smem + ldmatrix;
// W fragments staged ONCE in smem (64KB, lane-fastest, conflict-free LDS.128).
__global__ __launch_bounds__(256) void k_gemm_mma(
    const void* __restrict__ Ain, int a_bf16,
    const uint2* __restrict__ wfrag,
    __nv_bfloat16* __restrict__ xwh)
{
    extern __shared__ __align__(16) char smem[];
    uint4* sW = (uint4*)smem;                                   // 4096 uint4 = 64KB
    __nv_bfloat16* sA = (__nv_bfloat16*)(smem + 64 * 1024);     // 32KB
    int tid = threadIdx.x;
    int lane = tid & 31;
    int w = tid >> 5;
    int rb = blockIdx.x * 128;

    // --- stage W fragments (once) ---
    {
        const uint4* src = (const uint4*)wfrag;
#pragma unroll
        for (int t = 0; t < 16; t++) sW[tid + t * 256] = src[tid + t * 256];
    }
    // --- stage A tile as bf16 (thread = half a row) ---
    {
        int row = tid >> 1;
        int hf = tid & 1;
        int gr = rb + row;
        if (a_bf16) {
            const uint4* src = (const uint4*)Ain + (size_t)gr * 16 + hf * 8;
#pragma unroll
            for (int c = 0; c < 8; c++) {
                uint4 v = make_uint4(0u, 0u, 0u, 0u);
                if (gr < N_NODES) v = src[c];
                int ch = hf * 8 + c;
                *(uint4*)&sA[row * 128 + (ch ^ (row & 7)) * 8] = v;
            }
        } else {
            const float4* src = (const float4*)Ain + (size_t)gr * 32 + hf * 16;
#pragma unroll
            for (int c = 0; c < 8; c++) {
                uint4 v = make_uint4(0u, 0u, 0u, 0u);
                if (gr < N_NODES) {
                    float4 f0 = src[2 * c];
                    float4 f1 = src[2 * c + 1];
                    v.x = pack_bf16(f0.x, f0.y);
                    v.y = pack_bf16(f0.z, f0.w);
                    v.z = pack_bf16(f1.x, f1.y);
                    v.w = pack_bf16(f1.z, f1.w);
                }
                int ch = hf * 8 + c;
                *(uint4*)&sA[row * 128 + (ch ^ (row & 7)) * 8] = v;
            }
        }
    }
    __syncthreads();

    float acc[16][4];
#pragma unroll
    for (int i = 0; i < 16; i++)
#pragma unroll
        for (int j = 0; j < 4; j++) acc[i][j] = 0.f;

    int m = lane >> 3, r_in = lane & 7;
    int row_m = w * 16 + (m & 1) * 8 + r_in;

#pragma unroll
    for (int ks = 0; ks < 8; ks++) {
        unsigned a0, a1, a2, a3;
        int chunk = ks * 2 + (m >> 1);
        uint32_t addr = smem_u32(&sA[row_m * 128 + (chunk ^ r_in) * 8]);
        asm volatile("ldmatrix.sync.aligned.m8n8.x4.shared.b16 {%0,%1,%2,%3}, [%4];"
                     : "=r"(a0), "=r"(a1), "=r"(a2), "=r"(a3) : "r"(addr));
#pragma unroll
        for (int lvl = 0; lvl < 2; lvl++) {
#pragma unroll
            for (int np = 0; np < 8; np++) {
                uint4 bb = sW[((lvl * 8 + ks) * 8 + np) * 32 + lane];
                asm volatile(
                    "mma.sync.aligned.m16n8k16.row.col.f32.bf16.bf16.f32 "
                    "{%0,%1,%2,%3}, {%4,%5,%6,%7}, {%8,%9}, {%0,%1,%2,%3};"
                    : "+f"(acc[2 * np][0]), "+f"(acc[2 * np][1]),
                      "+f"(acc[2 * np][2]), "+f"(acc[2 * np][3])
                    : "r"(a0), "r"(a1), "r"(a2), "r"(a3), "r"(bb.x), "r"(bb.y));
                asm volatile(
                    "mma.sync.aligned.m16n8k16.row.col.f32.bf16.bf16.f32 "
                    "{%0,%1,%2,%3}, {%4,%5,%6,%7}, {%8,%9}, {%0,%1,%2,%3};"
                    : "+f"(acc[2 * np + 1][0]), "+f"(acc[2 * np + 1][1]),
                      "+f"(acc[2 * np + 1][2]), "+f"(acc[2 * np + 1][3])
                    : "r"(a0), "r"(a1), "r"(a2), "r"(a3), "r"(bb.z), "r"(bb.w));
            }
        }
    }
    __syncthreads();   // done reading sA; reuse as D staging

    // --- stage D (bf16) into swizzled smem ---
    {
        int g = lane >> 2, tg = lane & 3;
        int r0 = w * 16 + g;
        int r1 = r0 + 8;
#pragma unroll
        for (int nb = 0; nb < 16; nb++) {
            *(unsigned*)&sA[r0 * 128 + (nb ^ (r0 & 7)) * 8 + tg * 2] =
                pack_bf16(acc[nb][0], acc[nb][1]);
            *(unsigned*)&sA[r1 * 128 + (nb ^ (r1 & 7)) * 8 + tg * 2] =
                pack_bf16(acc[nb][2], acc[nb][3]);
        }
    }
    __syncthreads();

    // --- coalesced copy out ---
    {
        int row = tid >> 1;
        int hf = tid & 1;
        int gr = rb + row;
        if (gr < N_NODES) {
            uint4* dst = (uint4*)xwh + (size_t)gr * 16 + hf * 8;
#pragma unroll
            for (int c = 0; c < 8; c++) {
                int ch = hf * 8 + c;
                dst[c] = *(uint4*)&sA[row * 128 + (ch ^ (row & 7)) * 8];
            }
        }
    }
}

// ---------------- CSR aggregate (warp per node, bf16 in/out) ---------------
__device__ __forceinline__ void acc_bf16(float4& acc, uint2 v, float nw) {
    float f0 = __uint_as_float(v.x << 16);
    float f1 = __uint_as_float(v.x & 0xFFFF0000u);
    float f2 = __uint_as_float(v.y << 16);
    float f3 = __uint_as_float(v.y & 0xFFFF0000u);
    acc.x += f0 * nw; acc.y += f1 * nw; acc.z += f2 * nw; acc.w += f3 * nw;
}
__device__ __forceinline__ float meta_norm(unsigned m) {
    return __half2float(__ushort_as_half((unsigned short)(m >> 16)));
}

__global__ __launch_bounds__(256) void k_agg128(
    const __nv_bfloat16* __restrict__ xwh, const float* __restrict__ bias,
    __nv_bfloat16* __restrict__ h)
{
    int w = blockIdx.x * 8 + (threadIdx.x >> 5);
    int lane = threadIdx.x & 31;
    if (w >= N_NODES) return;
    const uint2* xw2 = (const uint2*)xwh;
    float d = g_dis[w];
    float4 acc = make_float4(0.f, 0.f, 0.f, 0.f);
    acc_bf16(acc, xw2[w * 32 + lane], d * d);
    int beg = g_off[w], end = g_off[w + 1];
    int e = beg;
    while ((e & 3) && e < end) {
        unsigned m = g_emeta[e];
        acc_bf16(acc, xw2[(int)(m & 0xFFFFu) * 32 + lane], meta_norm(m));
        e++;
    }
    for (; e + 4 <= end; e += 4) {
        uint4 mm = *(const uint4*)&g_emeta[e];
        uint2 v0 = xw2[(int)(mm.x & 0xFFFFu) * 32 + lane];
        uint2 v1 = xw2[(int)(mm.y & 0xFFFFu) * 32 + lane];
        uint2 v2 = xw2[(int)(mm.z & 0xFFFFu) * 32 + lane];
        uint2 v3 = xw2[(int)(mm.w & 0xFFFFu) * 32 + lane];
        acc_bf16(acc, v0, meta_norm(mm.x));
        acc_bf16(acc, v1, meta_norm(mm.y));
        acc_bf16(acc, v2, meta_norm(mm.z));
        acc_bf16(acc, v3, meta_norm(mm.w));
    }
    for (; e < end; e++) {
        unsigned m = g_emeta[e];
        acc_bf16(acc, xw2[(int)(m & 0xFFFFu) * 32 + lane], meta_norm(m));
    }
    float4 bb = ((const float4*)bias)[lane];
    acc.x = fmaxf(acc.x + bb.x, 0.f);
    acc.y = fmaxf(acc.y + bb.y, 0.f);
    acc.z = fmaxf(acc.z + bb.z, 0.f);
    acc.w = fmaxf(acc.w + bb.w, 0.f);
    uint2 st;
    st.x = pack_bf16(acc.x, acc.y);
    st.y = pack_bf16(acc.z, acc.w);
    ((uint2*)h)[w * 32 + lane] = st;
}

// --------- layer-3 collapse + fused finish (last block computes out) -------
#define WRED_BLOCKS ((N_NODES + 127) / 128)   // 391
__global__ __launch_bounds__(256) void k_wred(
    const __nv_bfloat16* __restrict__ h2, const float* __restrict__ W2,
    const float* __restrict__ b2, float* __restrict__ out)
{
    __shared__ float sv[256];
    __shared__ unsigned s_rank;
    int tid = threadIdx.x;
    int k = tid & 127;
    int hf = tid >> 7;
    float acc = 0.f;
    int m0 = blockIdx.x * 128;
    int mend = min(m0 + 128, N_NODES);
    for (int m = m0 + hf; m < mend; m += 2) {
        float d = g_dis[m];
        float wn = d * (g_cwa[m] + d);
        acc += wn * __bfloat162float(h2[m * HID + k]);
    }
    sv[tid] = acc;
    __syncthreads();
    if (hf == 0) atomicAdd(&g_v[k], acc + sv[128 + k]);
    __threadfence();
    __syncthreads();
    if (tid == 0) s_rank = atomicAdd(&g_done, 1u);
    __syncthreads();
    if (s_rank == WRED_BLOCKS - 1) {
        if (tid == 0) g_done = 0;
        __threadfence();
        if (tid < COUT) {
            float a = 0.f;
#pragma unroll 4
            for (int j = 0; j < HID; j++) a += __ldcg(&g_v[j]) * W2[j * COUT + tid];
            out[tid] = b2[tid] + a * (1.0f / (float)N_NODES);
        }
    }
}

// ---------------- launch ----------------------------------------------------
extern "C" void kernel_launch(void* const* d_in, const int* in_sizes, int n_in,
                              void* d_out, int out_size)
{
    const float* x  = (const float*)d_in[0];
    const void*  ei = d_in[1];
    const float* W0 = (const float*)d_in[2];
    const float* b0 = (const float*)d_in[3];
    const float* W1 = (const float*)d_in[4];
    const float* b1 = (const float*)d_in[5];
    const float* W2 = (const float*)d_in[6];
    const float* b2 = (const float*)d_in[7];
    float* out = (float*)d_out;

    float* bufA; cudaGetSymbolAddress((void**)&bufA, g_bufA);
    float* bufB; cudaGetSymbolAddress((void**)&bufB, g_bufB);
    uint2* wfrag; cudaGetSymbolAddress((void**)&wfrag, g_wfrag);

    const int gemmBlocks = (N_NODES + 127) / 128;   // 391
    const int aggBlocks  = (N_NODES + 7) / 8;       // 6250

    // Host-side attribute (not a stream op; safe under graph capture).
    cudaFuncSetAttribute(k_gemm_mma, cudaFuncAttributeMaxDynamicSharedMemorySize,
                         GEMM_SMEM);

    // --- fused CSR build + W fragment prep (1 launch) ---
    k_setup<<<SETUP_BLOCKS, 256>>>(ei, (int2*)bufA, W0, W1);

    __nv_bfloat16* xwh = (__nv_bfloat16*)bufA;
    __nv_bfloat16* hb  = (__nv_bfloat16*)bufB;

    // --- layer 1: x (fp32) -> hb (h1, bf16) ---
    k_gemm_mma<<<gemmBlocks, 256, GEMM_SMEM>>>(x, 0, wfrag, xwh);
    k_agg128<<<aggBlocks, 256>>>(xwh, b0, hb);

    // --- layer 2: hb (bf16) -> hb (h2, bf16) ---
    k_gemm_mma<<<gemmBlocks, 256, GEMM_SMEM>>>(hb, 1, wfrag + 8192, xwh);
    k_agg128<<<aggBlocks, 256>>>(xwh, b1, hb);

    // --- layer 3 (collapsed) + finish fused ---
    k_wred<<<WRED_BLOCKS, 256>>>(hb, W2, b2, out);
}

// round 13
// speedup vs baseline: 1.6754x; 1.0663x over previous
#include <cuda_runtime.h>
#include <cuda_bf16.h>
#include <cuda_fp16.h>
#include <cstdint>

#define N_NODES 50000
#define N_EDGES 800000
#define HID 128
#define COUT 40
#define SETUP_BLOCKS 148   // one block per SM: co-residency unconditional
#define NB_SCAN 196        // ceil(50000/256)
#define GEMM_SMEM (32 * 1024 + 32 * 1024)   // sW (32KB fp16) + sA (32KB fp16)

typedef unsigned long long ull;

// ---------------- device scratch (static, allocation-free) ----------------
__device__ float g_dis[N_NODES];
__device__ float g_cwa[N_NODES];         // sum over out-edges of dis[col]
__device__ int   g_cnt[N_NODES];
__device__ int   g_off[N_NODES + 1];
__device__ int   g_cur[N_NODES];
__device__ int   g_bsum[NB_SCAN];
__device__ __align__(16) unsigned g_emeta[N_EDGES]; // {fp16 norm | 16-bit src}
__device__ float g_v[HID];               // weighted h2 reduction
__device__ int   g_flag;                 // 1 = edge_index is int64, 0 = int32
__device__ unsigned g_barcnt;            // grid barrier arrive counter (self-reset)
__device__ volatile unsigned g_sense;    // grid barrier phase (monotonic across replays)
__device__ unsigned g_done;              // wred completion counter (self-reset)
__device__ float g_bufA[N_NODES * HID];  // xw fp16 / int2 staging
__device__ float g_bufB[N_NODES * HID];  // h fp16 scratch
// W fragments (fp16, single level), smem-image layout per layer:
//   uint2 idx = layer*4096 + ((ks*8+np)*32+lane)*2 + half   (half = nb&1)
__device__ __align__(16) uint2 g_wfrag[2 * 4096];

__device__ __forceinline__ void decode_edge(const void* ei, int e, int& r, int& c) {
    if (g_flag) {
        const long long* p = (const long long*)ei;
        r = (int)p[e];
        c = (int)p[N_EDGES + e];
    } else {
        const int* p = (const int*)ei;
        r = p[e];
        c = p[N_EDGES + e];
    }
}

__device__ __forceinline__ uint32_t smem_u32(const void* p) {
    uint32_t a;
    asm("{ .reg .u64 t; cvta.to.shared.u64 t, %1; cvt.u32.u64 %0, t; }" : "=r"(a) : "l"(p));
    return a;
}
__device__ __forceinline__ unsigned pack_h(float a, float b) {
    __half2 t = __floats2half2_rn(a, b);
    return *(unsigned*)&t;
}

// Software grid barrier; 148 blocks = 1/SM, co-resident by construction.
__device__ __forceinline__ void grid_bar(unsigned target) {
    __threadfence();
    __syncthreads();
    if (threadIdx.x == 0) {
        unsigned my = atomicAdd(&g_barcnt, 1u);
        if (my == SETUP_BLOCKS - 1) {
            g_barcnt = 0;
            __threadfence();
            g_sense = target;
        } else {
            while (g_sense != target) { __nanosleep(64); }
        }
        __threadfence();
    }
    __syncthreads();
}

// ---------------- fused CSR-build + W-fragment prep (one launch) -----------
__global__ __launch_bounds__(256) void k_setup(const void* __restrict__ ei,
                                               int2* __restrict__ stage,
                                               const float* __restrict__ W0,
                                               const float* __restrict__ W1)
{
    __shared__ int s[256];
    int tid = threadIdx.x;
    int b = blockIdx.x;
    unsigned base = g_sense;

    // --- phase 0: zero counters, detect index width, build W fragments ---
    for (int i = b * 256 + tid; i < N_NODES; i += SETUP_BLOCKS * 256) {
        g_cnt[i] = 0;
        g_cwa[i] = 0.f;
    }
    if (b == 0 && tid < HID) g_v[tid] = 0.f;
    if (b == 0 && tid < 32) {
        const unsigned* u = (const unsigned*)ei;
        unsigned nz = (u[2 * tid + 1] != 0u) | (u[2 * (tid + 32) + 1] != 0u);
        unsigned any = __ballot_sync(0xffffffffu, nz);
        if (tid == 0) g_flag = (any == 0u) ? 1 : 0;
    }
    // W fragments (fp16): 8192 slots = (layer,nb,ks,lane), one uint2 each.
    for (int lin = b * 256 + tid; lin < 8192; lin += SETUP_BLOCKS * 256) {
        int lane = lin & 31;
        int ks = (lin >> 5) & 7;
        int nb = (lin >> 8) & 15;
        int layer = (lin >> 12) & 1;
        const float* W = layer ? W1 : W0;
        int g = lane >> 2, tg = lane & 3;
        int n = nb * 8 + g;
        int k0 = ks * 16 + tg * 2;
        unsigned b0 = pack_h(W[k0 * 128 + n],       W[(k0 + 1) * 128 + n]);
        unsigned b1 = pack_h(W[(k0 + 8) * 128 + n], W[(k0 + 9) * 128 + n]);
        int np = nb >> 1, half = nb & 1;
        int idx = layer * 4096 + ((ks * 8 + np) * 32 + lane) * 2 + half;
        g_wfrag[idx] = make_uint2(b0, b1);
    }
    grid_bar(base + 1);

    // --- phase 1: decode + histogram ---
    for (int e = b * 256 + tid; e < N_EDGES; e += SETUP_BLOCKS * 256) {
        int r, c;
        decode_edge(ei, e, r, c);
        stage[e] = make_int2(r, c);
        atomicAdd(&g_cnt[c], 1);
    }
    grid_bar(base + 2);

    // --- phase 2: local scans (grid-stride over 196 chunks) ---
    for (int ch = b; ch < NB_SCAN; ch += SETUP_BLOCKS) {
        int i = ch * 256 + tid;
        int v = (i < N_NODES) ? g_cnt[i] : 0;
        s[tid] = v;
        __syncthreads();
        for (int d = 1; d < 256; d <<= 1) {
            int t = (tid >= d) ? s[tid - d] : 0;
            __syncthreads();
            s[tid] += t;
            __syncthreads();
        }
        if (i < N_NODES) g_off[i] = s[tid] - v;
        if (tid == 255) g_bsum[ch] = s[255];
        __syncthreads();
    }
    grid_bar(base + 3);

    // --- phase 3: redundant chunk-sum scan, apply prefixes, derive dis/cur ---
    {
        int v = (tid < NB_SCAN) ? g_bsum[tid] : 0;
        s[tid] = v;
        __syncthreads();
        for (int d = 1; d < 256; d <<= 1) {
            int t = (tid >= d) ? s[tid - d] : 0;
            __syncthreads();
            s[tid] += t;
            __syncthreads();
        }
        for (int ch = b; ch < NB_SCAN; ch += SETUP_BLOCKS) {
            int pre = (ch == 0) ? 0 : s[ch - 1];
            int i = ch * 256 + tid;
            if (i < N_NODES) {
                int o = g_off[i] + pre;
                g_off[i] = o;
                g_cur[i] = o;
                g_dis[i] = rsqrtf((float)g_cnt[i] + 1.0f);
            }
            if (i == 0) g_off[N_NODES] = N_EDGES;
        }
    }
    grid_bar(base + 4);

    // --- phase 4: fill CSR + layer-3 collapse weights ---
    for (int e = b * 256 + tid; e < N_EDGES; e += SETUP_BLOCKS * 256) {
        int2 rc = stage[e];
        float dr = g_dis[rc.x], dc = g_dis[rc.y];
        int pos = atomicAdd(&g_cur[rc.y], 1);
        unsigned short hn = __half_as_ushort(__float2half_rn(dr * dc));
        g_emeta[pos] = (unsigned)rc.x | ((unsigned)hn << 16);
        atomicAdd(&g_cwa[rc.x], dc);
    }
}

// ---------------- mma.sync GEMM: [N,128] @ [128,128] -> xw fp16 ------------
// 128x128 tile, 8 warps; A staged fp16 in swizzled smem + ldmatrix;
// W fragments (fp16, single pass) staged once in smem, conflict-free LDS.128.
__global__ __launch_bounds__(256) void k_gemm_mma(
    const void* __restrict__ Ain, int a_f16,
    const uint2* __restrict__ wfrag,
    __half* __restrict__ xwh)
{
    extern __shared__ __align__(16) char smem[];
    uint4* sW = (uint4*)smem;                           // 2048 uint4 = 32KB
    __half* sA = (__half*)(smem + 32 * 1024);           // 32KB
    int tid = threadIdx.x;
    int lane = tid & 31;
    int w = tid >> 5;
    int rb = blockIdx.x * 128;

    // --- stage W fragments (once) ---
    {
        const uint4* src = (const uint4*)wfrag;
#pragma unroll
        for (int t = 0; t < 8; t++) sW[tid + t * 256] = src[tid + t * 256];
    }
    // --- stage A tile as fp16 (thread = half a row) ---
    {
        int row = tid >> 1;
        int hf = tid & 1;
        int gr = rb + row;
        if (a_f16) {
            const uint4* src = (const uint4*)Ain + (size_t)gr * 16 + hf * 8;
#pragma unroll
            for (int c = 0; c < 8; c++) {
                uint4 v = make_uint4(0u, 0u, 0u, 0u);
                if (gr < N_NODES) v = src[c];
                int ch = hf * 8 + c;
                *(uint4*)&sA[row * 128 + (ch ^ (row & 7)) * 8] = v;
            }
        } else {
            const float4* src = (const float4*)Ain + (size_t)gr * 32 + hf * 16;
#pragma unroll
            for (int c = 0; c < 8; c++) {
                uint4 v = make_uint4(0u, 0u, 0u, 0u);
                if (gr < N_NODES) {
                    float4 f0 = src[2 * c];
                    float4 f1 = src[2 * c + 1];
                    v.x = pack_h(f0.x, f0.y);
                    v.y = pack_h(f0.z, f0.w);
                    v.z = pack_h(f1.x, f1.y);
                    v.w = pack_h(f1.z, f1.w);
                }
                int ch = hf * 8 + c;
                *(uint4*)&sA[row * 128 + (ch ^ (row & 7)) * 8] = v;
            }
        }
    }
    __syncthreads();

    float acc[16][4];
#pragma unroll
    for (int i = 0; i < 16; i++)
#pragma unroll
        for (int j = 0; j < 4; j++) acc[i][j] = 0.f;

    int m = lane >> 3, r_in = lane & 7;
    int row_m = w * 16 + (m & 1) * 8 + r_in;

#pragma unroll
    for (int ks = 0; ks < 8; ks++) {
        unsigned a0, a1, a2, a3;
        int chunk = ks * 2 + (m >> 1);
        uint32_t addr = smem_u32(&sA[row_m * 128 + (chunk ^ r_in) * 8]);
        asm volatile("ldmatrix.sync.aligned.m8n8.x4.shared.b16 {%0,%1,%2,%3}, [%4];"
                     : "=r"(a0), "=r"(a1), "=r"(a2), "=r"(a3) : "r"(addr));
#pragma unroll
        for (int np = 0; np < 8; np++) {
            uint4 bb = sW[(ks * 8 + np) * 32 + lane];
            asm volatile(
                "mma.sync.aligned.m16n8k16.row.col.f32.f16.f16.f32 "
                "{%0,%1,%2,%3}, {%4,%5,%6,%7}, {%8,%9}, {%0,%1,%2,%3};"
                : "+f"(acc[2 * np][0]), "+f"(acc[2 * np][1]),
                  "+f"(acc[2 * np][2]), "+f"(acc[2 * np][3])
                : "r"(a0), "r"(a1), "r"(a2), "r"(a3), "r"(bb.x), "r"(bb.y));
            asm volatile(
                "mma.sync.aligned.m16n8k16.row.col.f32.f16.f16.f32 "
                "{%0,%1,%2,%3}, {%4,%5,%6,%7}, {%8,%9}, {%0,%1,%2,%3};"
                : "+f"(acc[2 * np + 1][0]), "+f"(acc[2 * np + 1][1]),
                  "+f"(acc[2 * np + 1][2]), "+f"(acc[2 * np + 1][3])
                : "r"(a0), "r"(a1), "r"(a2), "r"(a3), "r"(bb.z), "r"(bb.w));
        }
    }
    __syncthreads();   // done reading sA; reuse as D staging

    // --- stage D (fp16) into swizzled smem ---
    {
        int g = lane >> 2, tg = lane & 3;
        int r0 = w * 16 + g;
        int r1 = r0 + 8;
#pragma unroll
        for (int nb = 0; nb < 16; nb++) {
            *(unsigned*)&sA[r0 * 128 + (nb ^ (r0 & 7)) * 8 + tg * 2] =
                pack_h(acc[nb][0], acc[nb][1]);
            *(unsigned*)&sA[r1 * 128 + (nb ^ (r1 & 7)) * 8 + tg * 2] =
                pack_h(acc[nb][2], acc[nb][3]);
        }
    }
    __syncthreads();

    // --- coalesced copy out ---
    {
        int row = tid >> 1;
        int hf = tid & 1;
        int gr = rb + row;
        if (gr < N_NODES) {
            uint4* dst = (uint4*)xwh + (size_t)gr * 16 + hf * 8;
#pragma unroll
            for (int c = 0; c < 8; c++) {
                int ch = hf * 8 + c;
                dst[c] = *(uint4*)&sA[row * 128 + (ch ^ (row & 7)) * 8];
            }
        }
    }
}

// ---------------- CSR aggregate (warp per node, fp16 in/out) ---------------
__device__ __forceinline__ void acc_h(float4& acc, uint2 v, float nw) {
    float2 f01 = __half22float2(*(__half2*)&v.x);
    float2 f23 = __half22float2(*(__half2*)&v.y);
    acc.x += f01.x * nw; acc.y += f01.y * nw;
    acc.z += f23.x * nw; acc.w += f23.y * nw;
}
__device__ __forceinline__ float meta_norm(unsigned m) {
    return __half2float(__ushort_as_half((unsigned short)(m >> 16)));
}

__global__ __launch_bounds__(256) void k_agg128(
    const __half* __restrict__ xwh, const float* __restrict__ bias,
    __half* __restrict__ h)
{
    int w = blockIdx.x * 8 + (threadIdx.x >> 5);
    int lane = threadIdx.x & 31;
    if (w >= N_NODES) return;
    const uint2* xw2 = (const uint2*)xwh;
    float d = g_dis[w];
    float4 acc = make_float4(0.f, 0.f, 0.f, 0.f);
    acc_h(acc, xw2[w * 32 + lane], d * d);
    int beg = g_off[w], end = g_off[w + 1];
    int e = beg;
    while ((e & 3) && e < end) {
        unsigned m = g_emeta[e];
        acc_h(acc, xw2[(int)(m & 0xFFFFu) * 32 + lane], meta_norm(m));
        e++;
    }
    for (; e + 4 <= end; e += 4) {
        uint4 mm = *(const uint4*)&g_emeta[e];
        uint2 v0 = xw2[(int)(mm.x & 0xFFFFu) * 32 + lane];
        uint2 v1 = xw2[(int)(mm.y & 0xFFFFu) * 32 + lane];
        uint2 v2 = xw2[(int)(mm.z & 0xFFFFu) * 32 + lane];
        uint2 v3 = xw2[(int)(mm.w & 0xFFFFu) * 32 + lane];
        acc_h(acc, v0, meta_norm(mm.x));
        acc_h(acc, v1, meta_norm(mm.y));
        acc_h(acc, v2, meta_norm(mm.z));
        acc_h(acc, v3, meta_norm(mm.w));
    }
    for (; e < end; e++) {
        unsigned m = g_emeta[e];
        acc_h(acc, xw2[(int)(m & 0xFFFFu) * 32 + lane], meta_norm(m));
    }
    float4 bb = ((const float4*)bias)[lane];
    acc.x = fmaxf(acc.x + bb.x, 0.f);
    acc.y = fmaxf(acc.y + bb.y, 0.f);
    acc.z = fmaxf(acc.z + bb.z, 0.f);
    acc.w = fmaxf(acc.w + bb.w, 0.f);
    uint2 st;
    st.x = pack_h(acc.x, acc.y);
    st.y = pack_h(acc.z, acc.w);
    ((uint2*)h)[w * 32 + lane] = st;
}

// --------- layer-3 collapse + fused finish (last block computes out) -------
#define WRED_BLOCKS ((N_NODES + 127) / 128)   // 391
__global__ __launch_bounds__(256) void k_wred(
    const __half* __restrict__ h2, const float* __restrict__ W2,
    const float* __restrict__ b2, float* __restrict__ out)
{
    __shared__ float sv[256];
    __shared__ unsigned s_rank;
    int tid = threadIdx.x;
    int k = tid & 127;
    int hf = tid >> 7;
    float acc = 0.f;
    int m0 = blockIdx.x * 128;
    int mend = min(m0 + 128, N_NODES);
    for (int m = m0 + hf; m < mend; m += 2) {
        float d = g_dis[m];
        float wn = d * (g_cwa[m] + d);
        acc += wn * __half2float(h2[m * HID + k]);
    }
    sv[tid] = acc;
    __syncthreads();
    if (hf == 0) atomicAdd(&g_v[k], acc + sv[128 + k]);
    __threadfence();
    __syncthreads();
    if (tid == 0) s_rank = atomicAdd(&g_done, 1u);
    __syncthreads();
    if (s_rank == WRED_BLOCKS - 1) {
        if (tid == 0) g_done = 0;
        __threadfence();
        if (tid < COUT) {
            float a = 0.f;
#pragma unroll 4
            for (int j = 0; j < HID; j++) a += __ldcg(&g_v[j]) * W2[j * COUT + tid];
            out[tid] = b2[tid] + a * (1.0f / (float)N_NODES);
        }
    }
}

// ---------------- launch ----------------------------------------------------
extern "C" void kernel_launch(void* const* d_in, const int* in_sizes, int n_in,
                              void* d_out, int out_size)
{
    const float* x  = (const float*)d_in[0];
    const void*  ei = d_in[1];
    const float* W0 = (const float*)d_in[2];
    const float* b0 = (const float*)d_in[3];
    const float* W1 = (const float*)d_in[4];
    const float* b1 = (const float*)d_in[5];
    const float* W2 = (const float*)d_in[6];
    const float* b2 = (const float*)d_in[7];
    float* out = (float*)d_out;

    float* bufA; cudaGetSymbolAddress((void**)&bufA, g_bufA);
    float* bufB; cudaGetSymbolAddress((void**)&bufB, g_bufB);
    uint2* wfrag; cudaGetSymbolAddress((void**)&wfrag, g_wfrag);

    const int gemmBlocks = (N_NODES + 127) / 128;   // 391
    const int aggBlocks  = (N_NODES + 7) / 8;       // 6250

    cudaFuncSetAttribute(k_gemm_mma, cudaFuncAttributeMaxDynamicSharedMemorySize,
                         GEMM_SMEM);

    // --- fused CSR build + W fragment prep (1 launch) ---
    k_setup<<<SETUP_BLOCKS, 256>>>(ei, (int2*)bufA, W0, W1);

    __half* xwh = (__half*)bufA;
    __half* hb  = (__half*)bufB;

    // --- layer 1: x (fp32) -> hb (h1, fp16) ---
    k_gemm_mma<<<gemmBlocks, 256, GEMM_SMEM>>>(x, 0, wfrag, xwh);
    k_agg128<<<aggBlocks, 256>>>(xwh, b0, hb);

    // --- layer 2: hb (fp16) -> hb (h2, fp16) ---
    k_gemm_mma<<<gemmBlocks, 256, GEMM_SMEM>>>(hb, 1, wfrag + 4096, xwh);
    k_agg128<<<aggBlocks, 256>>>(xwh, b1, hb);

    // --- layer 3 (collapsed) + finish fused ---
    k_wred<<<WRED_BLOCKS, 256>>>(hb, W2, b2, out);
}